// round 1
// baseline (speedup 1.0000x reference)
#include <cuda_runtime.h>
#include <math.h>

// ---------------- problem constants ----------------
#define BATCH 2048
#define IMG   28
#define HC    32
#define LC    16
#define WID   64
#define HID   64
#define LIS   22                 // 28 - 3*(3-1)
#define FLAT  (LIS*LIS*HC)       // 15488
#define BLK   (WID*LC)           // 1024
#define OUT3  (3*BLK + WID)      // 3136
#define NSTEP 20
#define NTAB  (2*NSTEP + 1)      // 41 distinct times

// ---------------- scratch (device globals; no runtime alloc) ----------------
__device__ float g_bufA[(size_t)BATCH*HC*26*26];  // 26x26 activations
__device__ float g_bufB[(size_t)BATCH*HC*24*24];  // 24x24 activations
__device__ float g_bufC[(size_t)BATCH*HC*22*22];  // 22x22 activations (h2 / decoder out)
__device__ float g_z1[BATCH*LC];
__device__ float g_val[BATCH];
__device__ float g_W [NTAB*WID*LC];
__device__ float g_U [NTAB*WID*LC];
__device__ float g_Bb[NTAB*WID];
__device__ float g_s [NTAB*WID];

// ---------------- generic 3x3 conv / transposed-conv ----------------
// TRANS=false: VALID conv, weights [COUT][CIN][3][3]
// TRANS=true : full-padded conv with flipped+transposed weights, i.e. convT,
//              weights [CIN][COUT][3][3], tap (ky,kx) uses w[ci][oc][2-ky][2-kx]
template<int INH, int INW, int CIN, int COUT, int OCPB, bool TRANS, bool TANH>
__global__ __launch_bounds__(256)
void conv3_kernel(const float* __restrict__ in, const float* __restrict__ w,
                  const float* __restrict__ bias, float* __restrict__ out)
{
    constexpr int OUTH = TRANS ? INH + 2 : INH - 2;
    constexpr int OUTW = TRANS ? INW + 2 : INW - 2;
    constexpr int TH = OUTH + 2, TW = OUTW + 2;   // padded tile dims
    constexpr int NPIX = OUTH * OUTW;
    constexpr int NT = 256;
    constexpr int PIXPT = (NPIX + NT - 1) / NT;
    constexpr int PAD = TRANS ? 2 : 0;

    __shared__ float tile[TH * TW];
    __shared__ float wsm[CIN * OCPB * 9];

    const int n   = blockIdx.x;
    const int ocg = blockIdx.y * OCPB;
    const int tid = threadIdx.x;

    // load all weights for this block once
    for (int i = tid; i < CIN * OCPB * 9; i += NT) {
        int ci  = i / (OCPB * 9);
        int r   = i % (OCPB * 9);
        int ocl = r / 9;
        int k   = r % 9;
        int ky = k / 3, kx = k % 3;
        float wv;
        if (TRANS)
            wv = w[((ci * COUT + (ocg + ocl)) * 3 + (2 - ky)) * 3 + (2 - kx)];
        else
            wv = w[(((ocg + ocl) * CIN + ci) * 3 + ky) * 3 + kx];
        wsm[(ci * OCPB + ocl) * 9 + k] = wv;
    }

    // per-thread output pixel coordinates
    int py[PIXPT], px[PIXPT];
#pragma unroll
    for (int p = 0; p < PIXPT; p++) {
        int pix = tid + p * NT;
        py[p] = pix / OUTW;
        px[p] = pix % OUTW;
    }

    float acc[PIXPT][OCPB];
#pragma unroll
    for (int p = 0; p < PIXPT; p++)
#pragma unroll
        for (int o = 0; o < OCPB; o++) acc[p][o] = bias[ocg + o];

    for (int ci = 0; ci < CIN; ci++) {
        __syncthreads();
        const float* ip = in + ((size_t)n * CIN + ci) * (INH * INW);
        for (int i = tid; i < TH * TW; i += NT) {
            int ty = i / TW, tx = i % TW;
            int iy = ty - PAD, ix = tx - PAD;
            float v = 0.f;
            if (!TRANS || ((unsigned)iy < (unsigned)INH && (unsigned)ix < (unsigned)INW))
                v = ip[iy * INW + ix];
            tile[i] = v;
        }
        __syncthreads();

        const float* wp = &wsm[ci * OCPB * 9];
#pragma unroll
        for (int k = 0; k < 9; k++) {
            const int ky = k / 3, kx = k % 3;
            float wr[OCPB];
#pragma unroll
            for (int o = 0; o < OCPB; o++) wr[o] = wp[o * 9 + k];
#pragma unroll
            for (int p = 0; p < PIXPT; p++) {
                int pix = tid + p * NT;
                if (PIXPT * NT == NPIX || pix < NPIX) {
                    float v = tile[(py[p] + ky) * TW + px[p] + kx];
#pragma unroll
                    for (int o = 0; o < OCPB; o++)
                        acc[p][o] = fmaf(v, wr[o], acc[p][o]);
                }
            }
        }
    }

#pragma unroll
    for (int p = 0; p < PIXPT; p++) {
        int pix = tid + p * NT;
        if (pix < NPIX) {
#pragma unroll
            for (int o = 0; o < OCPB; o++) {
                float v = acc[p][o];
                if (TANH) v = tanhf(v);
                out[((size_t)n * COUT + ocg + o) * NPIX + pix] = v;
            }
        }
    }
}

// ---------------- encoder: z1[n,l] = h2[n,:] @ elw + elb ----------------
// block: 16 batch rows x 16 latent dims, 256 threads, K staged in smem
__global__ __launch_bounds__(256)
void encoder_kernel(const float* __restrict__ h, const float* __restrict__ elw,
                    const float* __restrict__ elb, float* __restrict__ z1)
{
    __shared__ float sw[128 * LC];   // elw chunk [128 f][16 l]
    __shared__ float sc[16 * 128];   // h chunk   [16 n][128 f]
    const int tid = threadIdx.x;
    const int n0  = blockIdx.x * 16;
    const int nl  = tid / LC;
    const int l   = tid % LC;

    float acc = 0.f;
    for (int fc = 0; fc < FLAT; fc += 128) {
        __syncthreads();
        for (int i = tid; i < 128 * LC; i += 256) sw[i] = elw[fc * LC + i];
        for (int i = tid; i < 16 * 128; i += 256) {
            int nn = i / 128, ff = i % 128;
            sc[i] = h[(size_t)(n0 + nn) * FLAT + fc + ff];
        }
        __syncthreads();
#pragma unroll 8
        for (int ff = 0; ff < 128; ff++)
            acc = fmaf(sc[nl * 128 + ff], sw[ff * LC + l], acc);
    }
    z1[(n0 + nl) * LC + l] = acc + elb[l];
}

// ---------------- decoder: d[n,f] = tanh(z1[n,:] @ dlw[:,f] + dlb[f]) ----------------
__global__ __launch_bounds__(128)
void decoder_kernel(const float* __restrict__ z1, const float* __restrict__ dlw,
                    const float* __restrict__ dlb, float* __restrict__ d)
{
    __shared__ float zs[16 * LC];
    const int tid = threadIdx.x;
    const int f   = blockIdx.x * 128 + tid;
    const int n0  = blockIdx.y * 16;

    for (int i = tid; i < 16 * LC; i += 128) zs[i] = z1[n0 * LC + i];
    __syncthreads();

    float wv[LC];
#pragma unroll
    for (int l = 0; l < LC; l++) wv[l] = dlw[(size_t)l * FLAT + f];
    const float bb = dlb[f];

#pragma unroll
    for (int nn = 0; nn < 16; nn++) {
        float a = bb;
#pragma unroll
        for (int l = 0; l < LC; l++) a = fmaf(zs[nn * LC + l], wv[l], a);
        d[(size_t)(n0 + nn) * FLAT + f] = tanhf(a);
    }
}

// ---------------- hypernetwork tables for all 41 times ----------------
__global__ void hyper_kernel(const float* __restrict__ h1w, const float* __restrict__ h1b,
                             const float* __restrict__ h2w, const float* __restrict__ h2b,
                             const float* __restrict__ h3w, const float* __restrict__ h3b)
{
    const int j = blockIdx.x;           // time index
    const int w = threadIdx.x;          // 64 threads
    const float t = 10.0f - 0.25f * (float)j;

    __shared__ float p1[HID], p2[HID];
    __shared__ float Wl[BLK], Ul[BLK];

    p1[w] = tanhf(t * h1w[w] + h1b[w]);
    __syncthreads();
    {
        float a = h2b[w];
#pragma unroll 8
        for (int k = 0; k < HID; k++) a = fmaf(p1[k], h2w[k * HID + w], a);
        p2[w] = tanhf(a);
    }
    __syncthreads();

    for (int o = w; o < OUT3; o += HID) {
        float a = h3b[o];
#pragma unroll 8
        for (int k = 0; k < HID; k++) a = fmaf(p2[k], h3w[(size_t)k * OUT3 + o], a);
        if (o < BLK) {
            Wl[o] = a;
        } else if (o < 2 * BLK) {
            Ul[o - BLK] = a;                     // raw U (same thread will scale it)
        } else if (o < 3 * BLK) {
            Ul[o - 2 * BLK] *= 1.0f / (1.0f + expf(-a));   // * sigmoid(gate)
        } else {
            g_Bb[j * WID + (o - 3 * BLK)] = a;
        }
    }
    __syncthreads();

    for (int o = w; o < BLK; o += HID) {
        g_W[j * BLK + o] = Wl[o];
        g_U[j * BLK + o] = Ul[o];
    }
    {
        float sv = 0.f;
#pragma unroll
        for (int d = 0; d < LC; d++) sv = fmaf(Wl[w * LC + d], Ul[w * LC + d], sv);
        g_s[j * WID + w] = sv;
    }
}

// ---------------- CNF RK4 (1 thread = 1 sample) ----------------
__device__ __forceinline__ void feval(int j, const float z[LC], float dz[LC], float& dl)
{
    const float* __restrict__ W  = g_W  + j * BLK;
    const float* __restrict__ U  = g_U  + j * BLK;
    const float* __restrict__ Bb = g_Bb + j * WID;
    const float* __restrict__ s  = g_s  + j * WID;
#pragma unroll
    for (int d = 0; d < LC; d++) dz[d] = 0.f;
    float tr = 0.f;
    for (int w = 0; w < WID; w++) {
        float a = Bb[w];
#pragma unroll
        for (int d = 0; d < LC; d++) a = fmaf(z[d], W[w * LC + d], a);
        float hh = tanhf(a);
#pragma unroll
        for (int d = 0; d < LC; d++) dz[d] = fmaf(hh, U[w * LC + d], dz[d]);
        tr = fmaf(1.0f - hh * hh, s[w], tr);
    }
    const float inv = 1.0f / (float)WID;
#pragma unroll
    for (int d = 0; d < LC; d++) dz[d] *= inv;
    dl = -tr * inv;
}

__global__ __launch_bounds__(256)
void cnf_kernel(const float* __restrict__ z1, float* __restrict__ val)
{
    const int n = blockIdx.x * blockDim.x + threadIdx.x;
    float z[LC];
#pragma unroll
    for (int d = 0; d < LC; d++) z[d] = z1[n * LC + d];
    float lp = 0.f;
    const float dt = -0.5f;

    for (int i = 0; i < NSTEP; i++) {
        float kz[LC], zt[LC], acc[LC];
        float l1, li, lacc;

        feval(2 * i, z, kz, l1);
        lacc = l1;
#pragma unroll
        for (int d = 0; d < LC; d++) { acc[d] = kz[d]; zt[d] = fmaf(0.5f * dt, kz[d], z[d]); }

        feval(2 * i + 1, zt, kz, li);
        lacc += 2.f * li;
#pragma unroll
        for (int d = 0; d < LC; d++) { acc[d] += 2.f * kz[d]; zt[d] = fmaf(0.5f * dt, kz[d], z[d]); }

        feval(2 * i + 1, zt, kz, li);
        lacc += 2.f * li;
#pragma unroll
        for (int d = 0; d < LC; d++) { acc[d] += 2.f * kz[d]; zt[d] = fmaf(dt, kz[d], z[d]); }

        feval(2 * i + 2, zt, kz, li);
        lacc += li;
#pragma unroll
        for (int d = 0; d < LC; d++) z[d] = fmaf(dt / 6.0f, acc[d] + kz[d], z[d]);
        lp = fmaf(dt / 6.0f, lacc, lp);
    }

    float ss = 0.f;
#pragma unroll
    for (int d = 0; d < LC; d++) ss = fmaf(z[d], z[d], ss);
    // -0.5*(LC*log(2*pi) + LC*log(VAR) + ss/VAR)
    const float c = (float)LC * 1.8378770664093453f + (float)LC * logf(0.1f);
    float logp = -0.5f * (c + ss * 10.0f);
    val[n] = logp - lp;
}

// ---------------- final reduction: x_probs = mean(val) ----------------
__global__ __launch_bounds__(256)
void finalize_kernel(const float* __restrict__ val, float* __restrict__ outp)
{
    __shared__ float sm[256];
    const int tid = threadIdx.x;
    float a = 0.f;
    for (int i = tid; i < BATCH; i += 256) a += val[i];
    sm[tid] = a;
    __syncthreads();
    for (int s = 128; s > 0; s >>= 1) {
        if (tid < s) sm[tid] += sm[tid + s];
        __syncthreads();
    }
    if (tid == 0) outp[0] = sm[0] / (float)BATCH;
}

// ---------------- launcher ----------------
extern "C" void kernel_launch(void* const* d_in, const int* in_sizes, int n_in,
                              void* d_out, int out_size)
{
    const float* x   = (const float*)d_in[0];
    const float* c0w = (const float*)d_in[1];
    const float* c0b = (const float*)d_in[2];
    const float* c1w = (const float*)d_in[3];
    const float* c1b = (const float*)d_in[4];
    const float* c2w = (const float*)d_in[5];
    const float* c2b = (const float*)d_in[6];
    const float* elw = (const float*)d_in[7];
    const float* elb = (const float*)d_in[8];
    const float* dlw = (const float*)d_in[9];
    const float* dlb = (const float*)d_in[10];
    const float* t0w = (const float*)d_in[11];
    const float* t0b = (const float*)d_in[12];
    const float* t1w = (const float*)d_in[13];
    const float* t1b = (const float*)d_in[14];
    const float* t2w = (const float*)d_in[15];
    const float* t2b = (const float*)d_in[16];
    const float* h1w = (const float*)d_in[17];
    const float* h1b = (const float*)d_in[18];
    const float* h2w = (const float*)d_in[19];
    const float* h2b = (const float*)d_in[20];
    const float* h3w = (const float*)d_in[21];
    const float* h3b = (const float*)d_in[22];
    float* out = (float*)d_out;

    float *bufA, *bufB, *bufC, *z1, *val;
    cudaGetSymbolAddress((void**)&bufA, g_bufA);
    cudaGetSymbolAddress((void**)&bufB, g_bufB);
    cudaGetSymbolAddress((void**)&bufC, g_bufC);
    cudaGetSymbolAddress((void**)&z1,  g_z1);
    cudaGetSymbolAddress((void**)&val, g_val);

    // hypernetwork tables (independent of image path)
    hyper_kernel<<<NTAB, HID>>>(h1w, h1b, h2w, h2b, h3w, h3b);

    // encoder conv stack
    conv3_kernel<28,28, 1,HC,8,false,true><<<dim3(BATCH,4),256>>>(x,    c0w, c0b, bufA);
    conv3_kernel<26,26,HC,HC,8,false,true><<<dim3(BATCH,4),256>>>(bufA, c1w, c1b, bufB);
    conv3_kernel<24,24,HC,HC,8,false,true><<<dim3(BATCH,4),256>>>(bufB, c2w, c2b, bufC);

    // latent
    encoder_kernel<<<BATCH/16, 256>>>(bufC, elw, elb, z1);

    // CNF (needs hyper tables + z1)
    cnf_kernel<<<BATCH/256, 256>>>(z1, val);
    finalize_kernel<<<1, 256>>>(val, out + (size_t)BATCH*IMG*IMG);

    // decoder path (overwrites bufC after encoder has consumed it)
    decoder_kernel<<<dim3(FLAT/128, BATCH/16), 128>>>(z1, dlw, dlb, bufC);
    conv3_kernel<22,22,HC,HC,8,true,true ><<<dim3(BATCH,4),256>>>(bufC, t0w, t0b, bufB);
    conv3_kernel<24,24,HC,HC,8,true,true ><<<dim3(BATCH,4),256>>>(bufB, t1w, t1b, bufA);
    conv3_kernel<26,26,HC, 1,1,true,false><<<dim3(BATCH,1),256>>>(bufA, t2w, t2b, out);
}

// round 2
// speedup vs baseline: 2.1724x; 2.1724x over previous
#include <cuda_runtime.h>
#include <math.h>

// ---------------- problem constants ----------------
#define BATCH 2048
#define IMG   28
#define HC    32
#define LC    16
#define WID   64
#define HID   64
#define LIS   22                 // 28 - 3*(3-1)
#define FLAT  (LIS*LIS*HC)       // 15488
#define BLK   (WID*LC)           // 1024
#define OUT3  (3*BLK + WID)      // 3136
#define NSTEP 20
#define NTAB  (2*NSTEP + 1)      // 41 distinct times

// ---------------- scratch (device globals; no runtime alloc) ----------------
__device__ float g_bufA[(size_t)BATCH*HC*26*26];  // 26x26 activations
__device__ float g_bufB[(size_t)BATCH*HC*24*24];  // 24x24 activations
__device__ float g_bufC[(size_t)BATCH*HC*22*22];  // 22x22 activations (h2 / decoder in)
__device__ float g_z1[BATCH*LC];
__device__ float g_val[BATCH];
__device__ float g_W [NTAB*WID*LC];
__device__ float g_U [NTAB*WID*LC];
__device__ float g_Bb[NTAB*WID];
__device__ float g_s [NTAB*WID];

// =====================================================================
// conv3_v2: whole image (all CIN channels) + all weights staged in smem
// once, then a barrier-free FMA mainloop.
//   TRANS=false: VALID conv, weights [COUT][CIN][3][3]
//   TRANS=true : full-pad conv with flipped+transposed weights (convT),
//                weights [CIN][COUT][3][3], tap (ky,kx) -> w[ci][oc][2-ky][2-kx]
// Threads: 256 = GROUPS groups; each group owns OCPB=COUT/GROUPS channels,
// each thread owns PIXPT pixels (stride PIXT).
// =====================================================================
template<int INH, int INW, int CIN, int COUT, bool TRANS, bool TANH>
__global__ __launch_bounds__(256)
void conv3_v2(const float* __restrict__ in, const float* __restrict__ w,
              const float* __restrict__ bias, float* __restrict__ out)
{
    constexpr int OUTH = TRANS ? INH + 2 : INH - 2;
    constexpr int OUTW = TRANS ? INW + 2 : INW - 2;
    constexpr int TH = OUTH + 2, TW = OUTW + 2;   // staged (padded) tile dims
    constexpr int NPIX = OUTH * OUTW;
    constexpr int GROUPS = (COUT >= 16) ? 2 : 1;
    constexpr int OCPB = COUT / GROUPS;           // 16 or 1
    constexpr int PIXT = 256 / GROUPS;            // 128 or 256
    constexpr int PIXPT = (NPIX + PIXT - 1) / PIXT;
    constexpr int TILE_ELEMS = CIN * TH * TW;
    constexpr int W_ELEMS = CIN * COUT * 9;

    extern __shared__ float sm[];
    float* stile = sm;
    float* swts  = sm + TILE_ELEMS;

    const int n   = blockIdx.x;
    const int tid = threadIdx.x;

    // ---- stage weights (broadcast-friendly layout [ci][oc][k]) ----
    for (int i = tid; i < W_ELEMS; i += 256) {
        int ci = i / (COUT * 9);
        int r  = i % (COUT * 9);
        int oc = r / 9;
        int k  = r % 9;
        int ky = k / 3, kx = k % 3;
        float wv;
        if (TRANS)
            wv = w[((ci * COUT + oc) * 3 + (2 - ky)) * 3 + (2 - kx)];
        else
            wv = w[((oc * CIN + ci) * 3 + ky) * 3 + kx];
        swts[(ci * COUT + oc) * 9 + k] = wv;
    }

    // ---- stage input tile(s) ----
    if (!TRANS) {
        // tile == raw input exactly (TH=INH, TW=INW): vectorized copy
        const float4* ip = reinterpret_cast<const float4*>(in + (size_t)n * TILE_ELEMS);
        float4* tp = reinterpret_cast<float4*>(stile);
        for (int i = tid; i < TILE_ELEMS / 4; i += 256) tp[i] = ip[i];
    } else {
        const float* ip = in + (size_t)n * CIN * INH * INW;
        for (int i = tid; i < TILE_ELEMS; i += 256) {
            int ci = i / (TH * TW);
            int r  = i % (TH * TW);
            int ty = r / TW, tx = r % TW;
            int iy = ty - 2, ix = tx - 2;
            float v = 0.f;
            if ((unsigned)iy < (unsigned)INH && (unsigned)ix < (unsigned)INW)
                v = ip[ci * INH * INW + iy * INW + ix];
            stile[i] = v;
        }
    }
    __syncthreads();   // the ONLY barrier

    const int g   = tid / PIXT;
    const int lt  = tid % PIXT;
    const int ocb = g * OCPB;

    // per-thread pixel coords (invalid pixels clamped to 0 for safe smem reads)
    int pb[PIXPT];           // py*TW + px (base tap address)
    bool pv[PIXPT];
#pragma unroll
    for (int p = 0; p < PIXPT; p++) {
        int pix = lt + p * PIXT;
        pv[p] = (pix < NPIX);
        int cp = pv[p] ? pix : 0;
        pb[p] = (cp / OUTW) * TW + (cp % OUTW);
    }

    float acc[PIXPT][OCPB];
#pragma unroll
    for (int o = 0; o < OCPB; o++) {
        float bv = bias[ocb + o];
#pragma unroll
        for (int p = 0; p < PIXPT; p++) acc[p][o] = bv;
    }

#pragma unroll 1
    for (int ci = 0; ci < CIN; ci++) {
        const float* tp = stile + ci * TH * TW;
        const float* wp = swts + (ci * COUT + ocb) * 9;
#pragma unroll
        for (int k = 0; k < 9; k++) {
            const int off = (k / 3) * TW + (k % 3);
            float wr[OCPB];
#pragma unroll
            for (int o = 0; o < OCPB; o++) wr[o] = wp[o * 9 + k];   // broadcast LDS
#pragma unroll
            for (int p = 0; p < PIXPT; p++) {
                float v = tp[pb[p] + off];
#pragma unroll
                for (int o = 0; o < OCPB; o++)
                    acc[p][o] = fmaf(v, wr[o], acc[p][o]);
            }
        }
    }

#pragma unroll
    for (int p = 0; p < PIXPT; p++) {
        if (pv[p]) {
            int pix = lt + p * PIXT;
#pragma unroll
            for (int o = 0; o < OCPB; o++) {
                float v = acc[p][o];
                if (TANH) v = tanhf(v);
                out[((size_t)n * COUT + ocb + o) * NPIX + pix] = v;
            }
        }
    }
}

template<int INH, int INW, int CIN, int COUT, bool TRANS, bool TANH>
static void run_conv(const float* in, const float* w, const float* b, float* out)
{
    constexpr int OUTH = TRANS ? INH + 2 : INH - 2;
    constexpr int OUTW = TRANS ? INW + 2 : INW - 2;
    constexpr int TH = OUTH + 2, TW = OUTW + 2;
    constexpr size_t bytes = (size_t)(CIN * TH * TW + CIN * COUT * 9) * sizeof(float);
    cudaFuncSetAttribute(conv3_v2<INH,INW,CIN,COUT,TRANS,TANH>,
                         cudaFuncAttributeMaxDynamicSharedMemorySize, (int)bytes);
    conv3_v2<INH,INW,CIN,COUT,TRANS,TANH><<<BATCH, 256, bytes>>>(in, w, b, out);
}

// ---------------- encoder: z1[n,l] = h2[n,:] @ elw + elb ----------------
__global__ __launch_bounds__(256)
void encoder_kernel(const float* __restrict__ h, const float* __restrict__ elw,
                    const float* __restrict__ elb, float* __restrict__ z1)
{
    __shared__ float sw[128 * LC];   // elw chunk [128 f][16 l]
    __shared__ float sc[16 * 128];   // h chunk   [16 n][128 f]
    const int tid = threadIdx.x;
    const int n0  = blockIdx.x * 16;
    const int nl  = tid / LC;
    const int l   = tid % LC;

    float acc = 0.f;
    for (int fc = 0; fc < FLAT; fc += 128) {
        __syncthreads();
        for (int i = tid; i < 128 * LC; i += 256) sw[i] = elw[fc * LC + i];
        for (int i = tid; i < 16 * 128; i += 256) {
            int nn = i / 128, ff = i % 128;
            sc[i] = h[(size_t)(n0 + nn) * FLAT + fc + ff];
        }
        __syncthreads();
#pragma unroll 8
        for (int ff = 0; ff < 128; ff++)
            acc = fmaf(sc[nl * 128 + ff], sw[ff * LC + l], acc);
    }
    z1[(n0 + nl) * LC + l] = acc + elb[l];
}

// ---------------- decoder: d[n,f] = tanh(z1[n,:] @ dlw[:,f] + dlb[f]) ----------------
__global__ __launch_bounds__(128)
void decoder_kernel(const float* __restrict__ z1, const float* __restrict__ dlw,
                    const float* __restrict__ dlb, float* __restrict__ d)
{
    __shared__ float zs[16 * LC];
    const int tid = threadIdx.x;
    const int f   = blockIdx.x * 128 + tid;
    const int n0  = blockIdx.y * 16;

    for (int i = tid; i < 16 * LC; i += 128) zs[i] = z1[n0 * LC + i];
    __syncthreads();

    float wv[LC];
#pragma unroll
    for (int l = 0; l < LC; l++) wv[l] = dlw[(size_t)l * FLAT + f];
    const float bb = dlb[f];

#pragma unroll
    for (int nn = 0; nn < 16; nn++) {
        float a = bb;
#pragma unroll
        for (int l = 0; l < LC; l++) a = fmaf(zs[nn * LC + l], wv[l], a);
        d[(size_t)(n0 + nn) * FLAT + f] = tanhf(a);
    }
}

// ---------------- hypernetwork tables for all 41 times ----------------
__global__ void hyper_kernel(const float* __restrict__ h1w, const float* __restrict__ h1b,
                             const float* __restrict__ h2w, const float* __restrict__ h2b,
                             const float* __restrict__ h3w, const float* __restrict__ h3b)
{
    const int j = blockIdx.x;           // time index
    const int w = threadIdx.x;          // 64 threads
    const float t = 10.0f - 0.25f * (float)j;

    __shared__ float p1[HID], p2[HID];
    __shared__ float Wl[BLK], Ul[BLK];

    p1[w] = tanhf(t * h1w[w] + h1b[w]);
    __syncthreads();
    {
        float a = h2b[w];
#pragma unroll 8
        for (int k = 0; k < HID; k++) a = fmaf(p1[k], h2w[k * HID + w], a);
        p2[w] = tanhf(a);
    }
    __syncthreads();

    for (int o = w; o < OUT3; o += HID) {
        float a = h3b[o];
#pragma unroll 8
        for (int k = 0; k < HID; k++) a = fmaf(p2[k], h3w[(size_t)k * OUT3 + o], a);
        if (o < BLK) {
            Wl[o] = a;
        } else if (o < 2 * BLK) {
            Ul[o - BLK] = a;
        } else if (o < 3 * BLK) {
            Ul[o - 2 * BLK] *= 1.0f / (1.0f + expf(-a));   // * sigmoid(gate)
        } else {
            g_Bb[j * WID + (o - 3 * BLK)] = a;
        }
    }
    __syncthreads();

    for (int o = w; o < BLK; o += HID) {
        g_W[j * BLK + o] = Wl[o];
        g_U[j * BLK + o] = Ul[o];
    }
    {
        float sv = 0.f;
#pragma unroll
        for (int d = 0; d < LC; d++) sv = fmaf(Wl[w * LC + d], Ul[w * LC + d], sv);
        g_s[j * WID + w] = sv;
    }
}

// ---------------- CNF RK4: 16 lanes per sample ----------------
__device__ __forceinline__ void feval16(int j, int lane, const float z[LC],
                                        float dz[LC], float& dl)
{
    const float* __restrict__ W  = g_W  + j * BLK;
    const float* __restrict__ U  = g_U  + j * BLK;
    const float* __restrict__ Bb = g_Bb + j * WID;
    const float* __restrict__ s  = g_s  + j * WID;
#pragma unroll
    for (int d = 0; d < LC; d++) dz[d] = 0.f;
    float tr = 0.f;
#pragma unroll
    for (int ww = 0; ww < WID / 16; ww++) {
        const int w = lane + ww * 16;
        float a = Bb[w];
#pragma unroll
        for (int d = 0; d < LC; d++) a = fmaf(z[d], W[w * LC + d], a);
        float hh = tanhf(a);
#pragma unroll
        for (int d = 0; d < LC; d++) dz[d] = fmaf(hh, U[w * LC + d], dz[d]);
        tr = fmaf(1.0f - hh * hh, s[w], tr);
    }
    // butterfly reduce across the 16-lane group (bitwise identical per lane)
#pragma unroll
    for (int off = 8; off > 0; off >>= 1) {
#pragma unroll
        for (int d = 0; d < LC; d++)
            dz[d] += __shfl_xor_sync(0xffffffffu, dz[d], off, 16);
        tr += __shfl_xor_sync(0xffffffffu, tr, off, 16);
    }
    const float inv = 1.0f / (float)WID;
#pragma unroll
    for (int d = 0; d < LC; d++) dz[d] *= inv;
    dl = -tr * inv;
}

__global__ __launch_bounds__(256)
void cnf_kernel(const float* __restrict__ z1, float* __restrict__ val)
{
    const int tid  = threadIdx.x;
    const int lane = tid & 15;
    const int n    = blockIdx.x * 16 + (tid >> 4);

    float z[LC];
#pragma unroll
    for (int d = 0; d < LC; d++) z[d] = z1[n * LC + d];
    float lp = 0.f;
    const float dt = -0.5f;

    for (int i = 0; i < NSTEP; i++) {
        float kz[LC], zt[LC], acc[LC];
        float l1, li, lacc;

        feval16(2 * i, lane, z, kz, l1);
        lacc = l1;
#pragma unroll
        for (int d = 0; d < LC; d++) { acc[d] = kz[d]; zt[d] = fmaf(0.5f * dt, kz[d], z[d]); }

        feval16(2 * i + 1, lane, zt, kz, li);
        lacc += 2.f * li;
#pragma unroll
        for (int d = 0; d < LC; d++) { acc[d] += 2.f * kz[d]; zt[d] = fmaf(0.5f * dt, kz[d], z[d]); }

        feval16(2 * i + 1, lane, zt, kz, li);
        lacc += 2.f * li;
#pragma unroll
        for (int d = 0; d < LC; d++) { acc[d] += 2.f * kz[d]; zt[d] = fmaf(dt, kz[d], z[d]); }

        feval16(2 * i + 2, lane, zt, kz, li);
        lacc += li;
#pragma unroll
        for (int d = 0; d < LC; d++) z[d] = fmaf(dt / 6.0f, acc[d] + kz[d], z[d]);
        lp = fmaf(dt / 6.0f, lacc, lp);
    }

    if (lane == 0) {
        float ss = 0.f;
#pragma unroll
        for (int d = 0; d < LC; d++) ss = fmaf(z[d], z[d], ss);
        const float c = (float)LC * 1.8378770664093453f + (float)LC * logf(0.1f);
        float logp = -0.5f * (c + ss * 10.0f);
        val[n] = logp - lp;
    }
}

// ---------------- final reduction: x_probs = mean(val) ----------------
__global__ __launch_bounds__(256)
void finalize_kernel(const float* __restrict__ val, float* __restrict__ outp)
{
    __shared__ float sm[256];
    const int tid = threadIdx.x;
    float a = 0.f;
    for (int i = tid; i < BATCH; i += 256) a += val[i];
    sm[tid] = a;
    __syncthreads();
    for (int s = 128; s > 0; s >>= 1) {
        if (tid < s) sm[tid] += sm[tid + s];
        __syncthreads();
    }
    if (tid == 0) outp[0] = sm[0] / (float)BATCH;
}

// ---------------- launcher ----------------
extern "C" void kernel_launch(void* const* d_in, const int* in_sizes, int n_in,
                              void* d_out, int out_size)
{
    const float* x   = (const float*)d_in[0];
    const float* c0w = (const float*)d_in[1];
    const float* c0b = (const float*)d_in[2];
    const float* c1w = (const float*)d_in[3];
    const float* c1b = (const float*)d_in[4];
    const float* c2w = (const float*)d_in[5];
    const float* c2b = (const float*)d_in[6];
    const float* elw = (const float*)d_in[7];
    const float* elb = (const float*)d_in[8];
    const float* dlw = (const float*)d_in[9];
    const float* dlb = (const float*)d_in[10];
    const float* t0w = (const float*)d_in[11];
    const float* t0b = (const float*)d_in[12];
    const float* t1w = (const float*)d_in[13];
    const float* t1b = (const float*)d_in[14];
    const float* t2w = (const float*)d_in[15];
    const float* t2b = (const float*)d_in[16];
    const float* h1w = (const float*)d_in[17];
    const float* h1b = (const float*)d_in[18];
    const float* h2w = (const float*)d_in[19];
    const float* h2b = (const float*)d_in[20];
    const float* h3w = (const float*)d_in[21];
    const float* h3b = (const float*)d_in[22];
    float* out = (float*)d_out;

    float *bufA, *bufB, *bufC, *z1, *val;
    cudaGetSymbolAddress((void**)&bufA, g_bufA);
    cudaGetSymbolAddress((void**)&bufB, g_bufB);
    cudaGetSymbolAddress((void**)&bufC, g_bufC);
    cudaGetSymbolAddress((void**)&z1,  g_z1);
    cudaGetSymbolAddress((void**)&val, g_val);

    // hypernetwork tables (independent of image path)
    hyper_kernel<<<NTAB, HID>>>(h1w, h1b, h2w, h2b, h3w, h3b);

    // encoder conv stack
    run_conv<28,28, 1,HC,false,true>(x,    c0w, c0b, bufA);
    run_conv<26,26,HC,HC,false,true>(bufA, c1w, c1b, bufB);
    run_conv<24,24,HC,HC,false,true>(bufB, c2w, c2b, bufC);

    // latent
    encoder_kernel<<<BATCH/16, 256>>>(bufC, elw, elb, z1);

    // CNF (needs hyper tables + z1)
    cnf_kernel<<<BATCH*16/256, 256>>>(z1, val);
    finalize_kernel<<<1, 256>>>(val, out + (size_t)BATCH*IMG*IMG);

    // decoder path (overwrites bufC after encoder consumed it)
    decoder_kernel<<<dim3(FLAT/128, BATCH/16), 128>>>(z1, dlw, dlb, bufC);
    run_conv<22,22,HC,HC,true,true >(bufC, t0w, t0b, bufB);
    run_conv<24,24,HC,HC,true,true >(bufB, t1w, t1b, bufA);
    run_conv<26,26,HC, 1,true,false>(bufA, t2w, t2b, out);
}